// round 2
// baseline (speedup 1.0000x reference)
#include <cuda_runtime.h>

#define BB 4
#define CC 3
#define TF 103
#define HH 224
#define WW 224
#define W4 (WW / 4)                  // 56 float4 per row
#define ROWS_PER_BLK 8               // block = 56 x 8 = 448 threads
#define ITERS (HH / ROWS_PER_BLK)    // 28 rows per thread

__device__ int4 g_self_rect[BB * TF];  // x0, x1, y0, y1 (inclusive)
__device__ int4 g_idx_rect[BB * TF];
__device__ int  g_index[BB];

__global__ void rect_kernel(const float* __restrict__ bbox,
                            const int* __restrict__ index) {
    int i = blockIdx.x * blockDim.x + threadIdx.x;
    if (i >= BB * TF) return;
    int b = i / TF;
    int t = i % TF;

    const float* p = bbox + (size_t)(b * TF + t) * 8;
    float xmn = fminf(fminf(p[0], p[2]), fminf(p[4], p[6]));
    float xmx = fmaxf(fmaxf(p[0], p[2]), fmaxf(p[4], p[6]));
    float ymn = fminf(fminf(p[1], p[3]), fminf(p[5], p[7]));
    float ymx = fmaxf(fmaxf(p[1], p[3]), fmaxf(p[5], p[7]));
    int4 rs;
    rs.x = (int)fmaxf(xmn, 0.0f);
    rs.y = (int)fminf(xmx, (float)WW);
    rs.z = (int)fmaxf(ymn, 0.0f);
    rs.w = (int)fminf(ymx, (float)HH);
    g_self_rect[i] = rs;

    int ib = index[b];
    const float* q = bbox + (size_t)(ib * TF + t) * 8;
    float xmn2 = fminf(fminf(q[0], q[2]), fminf(q[4], q[6]));
    float xmx2 = fmaxf(fmaxf(q[0], q[2]), fmaxf(q[4], q[6]));
    float ymn2 = fminf(fminf(q[1], q[3]), fminf(q[5], q[7]));
    float ymx2 = fmaxf(fmaxf(q[1], q[3]), fmaxf(q[5], q[7]));
    int4 ri;
    ri.x = (int)xmn2;
    ri.y = (int)xmx2;
    ri.z = (int)ymn2;
    ri.w = (int)ymx2;
    g_idx_rect[i] = ri;

    if (t == 0) g_index[b] = ib;
}

// One block per (b,c,t) frame. Threads: w4 = tid%56 fixed, h strides by 8.
__global__ void __launch_bounds__(448)
fuse_kernel(const float4* __restrict__ v, float4* __restrict__ out) {
    unsigned int blk = blockIdx.x;            // (b*CC + c)*TF + t
    unsigned int t  = blk % TF;
    unsigned int bc = blk / TF;
    unsigned int c  = bc % CC;
    unsigned int b  = bc / CC;

    unsigned int w4 = threadIdx.x % W4;
    unsigned int hb = threadIdx.x / W4;       // 0..7

    int bt = (int)(b * TF + t);
    int4 rs = g_self_rect[bt];
    int4 ri = g_idx_rect[bt];
    unsigned int ib = (unsigned int)g_index[b];

    // frame bases (in float4 units)
    unsigned int frameS = blk * (HH * W4);
    unsigned int frameI = (((ib * CC + c) * TF + t)) * (HH * W4);

    // per-thread column predicates (fixed across the row loop)
    int x = (int)(w4 * 4);
    bool cS0 = (x     >= rs.x) & (x     <= rs.y);
    bool cS1 = (x + 1 >= rs.x) & (x + 1 <= rs.y);
    bool cS2 = (x + 2 >= rs.x) & (x + 2 <= rs.y);
    bool cS3 = (x + 3 >= rs.x) & (x + 3 <= rs.y);
    bool cSany = cS0 | cS1 | cS2 | cS3;

    bool cI0 = (x     >= ri.x) & (x     <= ri.y);
    bool cI1 = (x + 1 >= ri.x) & (x + 1 <= ri.y);
    bool cI2 = (x + 2 >= ri.x) & (x + 2 <= ri.y);
    bool cI3 = (x + 3 >= ri.x) & (x + 3 <= ri.y);

    unsigned int off = hb * W4 + w4;

    #pragma unroll 4
    for (int k = 0; k < ITERS; k++) {
        int h = (int)hb + k * ROWS_PER_BLK;
        bool rowS = (h >= rs.z) & (h <= rs.w);
        bool rowI = (h >= ri.z) & (h <= ri.w);

        bool m0 = rowS & cS0, m1 = rowS & cS1, m2 = rowS & cS2, m3 = rowS & cS3;
        bool i0 = rowI & cI0, i1 = rowI & cI1, i2 = rowI & cI2, i3 = rowI & cI3;

        bool needSelf = rowS & cSany;
        bool needIdx  = ((!m0) & (!i0)) | ((!m1) & (!i1)) |
                        ((!m2) & (!i2)) | ((!m3) & (!i3));

        float4 vs = make_float4(0.f, 0.f, 0.f, 0.f);
        float4 vi = make_float4(0.f, 0.f, 0.f, 0.f);
        if (needSelf) vs = __ldg(v + frameS + off);
        if (needIdx)  vi = __ldg(v + frameI + off);

        float4 o;
        o.x = m0 ? vs.x : (i0 ? 0.f : vi.x);
        o.y = m1 ? vs.y : (i1 ? 0.f : vi.y);
        o.z = m2 ? vs.z : (i2 ? 0.f : vi.z);
        o.w = m3 ? vs.w : (i3 ? 0.f : vi.w);
        out[frameS + off] = o;

        off += ROWS_PER_BLK * W4;
    }
}

extern "C" void kernel_launch(void* const* d_in, const int* in_sizes, int n_in,
                              void* d_out, int out_size) {
    const float* video = (const float*)d_in[0];
    const float* bbox  = (const float*)d_in[1];
    const int*   index = (const int*)d_in[2];
    float* out = (float*)d_out;

    rect_kernel<<<2, 256>>>(bbox, index);
    fuse_kernel<<<BB * CC * TF, 448>>>((const float4*)video, (float4*)out);
}

// round 3
// speedup vs baseline: 1.0135x; 1.0135x over previous
#include <cuda_runtime.h>

#define BB 4
#define CC 3
#define TF 103
#define HH 224
#define WW 224
#define W4 (WW / 4)                 // 56 float4 per row
#define H4 (HH / 4)                 // 56 row-groups of 4
#define FRAME4 (HH * W4)            // 12544 float4 per frame
#define NTHREADS (BB * CC * TF * H4 * W4)   // 3,876,096
#define BLK 256
#define GRID (NTHREADS / BLK)       // 15141 exact

// span-form rects per (b,t): {x0, x1-x0, y0, y1-y0}; membership = (u32)(p-p0)<=span
__device__ int4 g_self_rect[BB * TF];
__device__ int4 g_idx_rect[BB * TF];
__device__ int  g_index[BB];

__global__ void rect_kernel(const float* __restrict__ bbox,
                            const int* __restrict__ index) {
    int i = blockIdx.x * blockDim.x + threadIdx.x;
    if (i >= BB * TF) return;
    int b = i / TF;
    int t = i % TF;

    const float* p = bbox + (size_t)(b * TF + t) * 8;
    float xmn = fminf(fminf(p[0], p[2]), fminf(p[4], p[6]));
    float xmx = fmaxf(fmaxf(p[0], p[2]), fmaxf(p[4], p[6]));
    float ymn = fminf(fminf(p[1], p[3]), fminf(p[5], p[7]));
    float ymx = fmaxf(fmaxf(p[1], p[3]), fmaxf(p[5], p[7]));
    int x0 = (int)fmaxf(xmn, 0.0f);
    int x1 = (int)fminf(xmx, (float)WW);
    int y0 = (int)fmaxf(ymn, 0.0f);
    int y1 = (int)fminf(ymx, (float)HH);
    g_self_rect[i] = make_int4(x0, x1 - x0, y0, y1 - y0);

    int ib = index[b];
    const float* q = bbox + (size_t)(ib * TF + t) * 8;
    float xmn2 = fminf(fminf(q[0], q[2]), fminf(q[4], q[6]));
    float xmx2 = fmaxf(fmaxf(q[0], q[2]), fmaxf(q[4], q[6]));
    float ymn2 = fminf(fminf(q[1], q[3]), fminf(q[5], q[7]));
    float ymx2 = fmaxf(fmaxf(q[1], q[3]), fmaxf(q[5], q[7]));
    int ix0 = (int)xmn2, ix1 = (int)xmx2;
    int iy0 = (int)ymn2, iy1 = (int)ymx2;
    g_idx_rect[i] = make_int4(ix0, ix1 - ix0, iy0, iy1 - iy0);

    if (t == 0) g_index[b] = ib;
}

// Each thread: fixed (frame, w4), 4 consecutive rows 4*h4 .. 4*h4+3.
__global__ void __launch_bounds__(BLK)
fuse_kernel(const float4* __restrict__ v, float4* __restrict__ out) {
    unsigned int i = blockIdx.x * (unsigned)BLK + threadIdx.x;

    unsigned int w4 = i % W4;
    unsigned int r1 = i / W4;
    unsigned int h4 = r1 % H4;
    unsigned int fr = r1 / H4;          // frame = (b*CC + c)*TF + t
    unsigned int t  = fr % TF;
    unsigned int bc = fr / TF;
    unsigned int c  = bc % CC;
    unsigned int b  = bc / CC;

    int bt = (int)(b * TF + t);
    int4 rs = g_self_rect[bt];          // x0, spanX, y0, spanY
    int4 ri = g_idx_rect[bt];
    unsigned int ib = (unsigned int)g_index[b];

    unsigned int off0 = fr * FRAME4 + (h4 * 4) * W4 + w4;
    unsigned int offI = ((ib * CC + c) * TF + t) * FRAME4 + (h4 * 4) * W4 + w4;

    // column masks (fixed across the 4 rows)
    int x = (int)(w4 * 4);
    int dxS = x - rs.x;
    int dxI = x - ri.x;
    bool cS0 = (unsigned)(dxS    ) <= (unsigned)rs.y;
    bool cS1 = (unsigned)(dxS + 1) <= (unsigned)rs.y;
    bool cS2 = (unsigned)(dxS + 2) <= (unsigned)rs.y;
    bool cS3 = (unsigned)(dxS + 3) <= (unsigned)rs.y;
    bool cSany = cS0 | cS1 | cS2 | cS3;
    bool cI0 = (unsigned)(dxI    ) <= (unsigned)ri.y;
    bool cI1 = (unsigned)(dxI + 1) <= (unsigned)ri.y;
    bool cI2 = (unsigned)(dxI + 2) <= (unsigned)ri.y;
    bool cI3 = (unsigned)(dxI + 3) <= (unsigned)ri.y;

    int h0 = (int)(h4 * 4);

    #pragma unroll
    for (int k = 0; k < 4; k++) {
        int h = h0 + k;
        bool rowS = (unsigned)(h - rs.z) <= (unsigned)rs.w;
        bool rowI = (unsigned)(h - ri.z) <= (unsigned)ri.w;

        bool m0 = rowS & cS0, m1 = rowS & cS1, m2 = rowS & cS2, m3 = rowS & cS3;
        bool i0 = rowI & cI0, i1 = rowI & cI1, i2 = rowI & cI2, i3 = rowI & cI3;

        bool needSelf = rowS & cSany;
        bool needIdx  = !((m0 | i0) & (m1 | i1) & (m2 | i2) & (m3 | i3));

        float4 vs = make_float4(0.f, 0.f, 0.f, 0.f);
        float4 vi = make_float4(0.f, 0.f, 0.f, 0.f);
        if (needSelf) vs = __ldg(v + off0 + k * W4);
        if (needIdx)  vi = __ldg(v + offI + k * W4);

        float4 o;
        o.x = m0 ? vs.x : (i0 ? 0.f : vi.x);
        o.y = m1 ? vs.y : (i1 ? 0.f : vi.y);
        o.z = m2 ? vs.z : (i2 ? 0.f : vi.z);
        o.w = m3 ? vs.w : (i3 ? 0.f : vi.w);
        out[off0 + k * W4] = o;
    }
}

extern "C" void kernel_launch(void* const* d_in, const int* in_sizes, int n_in,
                              void* d_out, int out_size) {
    const float* video = (const float*)d_in[0];
    const float* bbox  = (const float*)d_in[1];
    const int*   index = (const int*)d_in[2];
    float* out = (float*)d_out;

    rect_kernel<<<2, 256>>>(bbox, index);
    fuse_kernel<<<GRID, BLK>>>((const float4*)video, (float4*)out);
}